// round 1
// baseline (speedup 1.0000x reference)
#include <cuda_runtime.h>
#include <math.h>

// ---------------- problem constants ----------------
#define BB      4
#define SS      2048
#define DD      1024
#define HH      16
#define DK      64
#define RR      16
#define SCALING 2.0f
#define NROWS   (BB * SS)          // 8192

// ---------------- device scratch (no allocs allowed) ----------------
__device__ float g_tq[NROWS * RR];
__device__ float g_tv[NROWS * RR];
__device__ float g_Q[BB * HH * SS * DK];   // [b*H+h][s][dk]
__device__ float g_K[BB * HH * SS * DK];
__device__ float g_V[BB * HH * SS * DK];
__device__ float g_O[NROWS * DD];          // [n][h*64+dk]

// ====================================================================
// Kernel 1: LoRA down-projections  t = (x @ A^T) * SCALING
// one warp per row n; lanes 0..15 -> Aq, lanes 16..31 -> Av
// ====================================================================
__global__ __launch_bounds__(256) void lora_t_kernel(
    const float* __restrict__ x,
    const float* __restrict__ Aq,
    const float* __restrict__ Av)
{
    int gtid = blockIdx.x * blockDim.x + threadIdx.x;
    int warp = gtid >> 5;
    int lane = gtid & 31;
    if (warp >= NROWS) return;

    const float* Arow = ((lane < 16) ? Aq : Av) + (size_t)(lane & 15) * DD;
    const float* xrow = x + (size_t)warp * DD;

    float acc = 0.0f;
    #pragma unroll 4
    for (int d = 0; d < DD; d += 4) {
        float4 xv = *(const float4*)(xrow + d);
        float4 av = *(const float4*)(Arow + d);
        acc += xv.x * av.x + xv.y * av.y + xv.z * av.z + xv.w * av.w;
    }
    acc *= SCALING;
    if (lane < 16) g_tq[warp * RR + lane]        = acc;
    else           g_tv[warp * RR + (lane & 15)] = acc;
}

// ====================================================================
// Kernel 2: fused QKV projection
// C[8192, 3072] = x @ [Wq;Wk;Wv]^T  (+ LoRA for Q,V in epilogue)
// 128x128 tile, BK=8, 256 threads, 8x8 micro-tile.
// Output written directly in [b*H+h][s][dk] layout.
// ====================================================================
__global__ __launch_bounds__(256) void qkv_gemm_kernel(
    const float* __restrict__ x,
    const float* __restrict__ Wq,
    const float* __restrict__ Wk,
    const float* __restrict__ Wv,
    const float* __restrict__ Bq,
    const float* __restrict__ Bv)
{
    __shared__ float As[8 * 128];
    __shared__ float Bs[8 * 128];
    __shared__ float Ts[16 * 128];   // lora t, transposed [p][n]
    __shared__ float Bl[16 * 128];   // lora B, transposed [p][i]

    int bx  = blockIdx.x;            // 0..23
    int mat = bx >> 3;               // 0=q, 1=k, 2=v
    int jn  = (bx & 7) * 128;        // column within matrix
    int bm  = blockIdx.y * 128;      // row tile

    const float* W = (mat == 0) ? Wq : (mat == 1) ? Wk : Wv;

    int tid = threadIdx.x;
    int tx  = tid & 15;
    int ty  = tid >> 4;
    int lr  = tid >> 1;              // load row 0..127
    int lk  = (tid & 1) * 4;         // load k 0 or 4

    const float* Ap = x + (size_t)(bm + lr) * DD + lk;
    const float* Bp = W + (size_t)(jn + lr) * DD + lk;

    float acc[8][8];
    #pragma unroll
    for (int i = 0; i < 8; i++)
        #pragma unroll
        for (int j = 0; j < 8; j++) acc[i][j] = 0.0f;

    for (int k0 = 0; k0 < DD; k0 += 8) {
        float4 av = *(const float4*)(Ap + k0);
        float4 bv = *(const float4*)(Bp + k0);
        As[(lk + 0) * 128 + lr] = av.x;
        As[(lk + 1) * 128 + lr] = av.y;
        As[(lk + 2) * 128 + lr] = av.z;
        As[(lk + 3) * 128 + lr] = av.w;
        Bs[(lk + 0) * 128 + lr] = bv.x;
        Bs[(lk + 1) * 128 + lr] = bv.y;
        Bs[(lk + 2) * 128 + lr] = bv.z;
        Bs[(lk + 3) * 128 + lr] = bv.w;
        __syncthreads();

        #pragma unroll
        for (int k = 0; k < 8; k++) {
            float a[8], b[8];
            *(float4*)(a)     = *(const float4*)&As[k * 128 + ty * 8];
            *(float4*)(a + 4) = *(const float4*)&As[k * 128 + ty * 8 + 4];
            *(float4*)(b)     = *(const float4*)&Bs[k * 128 + tx * 8];
            *(float4*)(b + 4) = *(const float4*)&Bs[k * 128 + tx * 8 + 4];
            #pragma unroll
            for (int i = 0; i < 8; i++)
                #pragma unroll
                for (int j = 0; j < 8; j++)
                    acc[i][j] = fmaf(a[i], b[j], acc[i][j]);
        }
        __syncthreads();
    }

    // -------- LoRA epilogue (Q and V only): acc += t_tile @ Bl_tile^T
    if (mat != 1) {
        const float* T  = (mat == 0) ? g_tq : g_tv;   // already scaled
        const float* Bm = (mat == 0) ? Bq : Bv;       // [inner, R]
        for (int idx = tid; idx < 128 * RR; idx += 256) {
            int n = idx >> 4;
            int p = idx & 15;
            Ts[p * 128 + n] = T [(size_t)bm * RR + idx];
            Bl[p * 128 + n] = Bm[(size_t)jn * RR + idx];
        }
        __syncthreads();
        #pragma unroll
        for (int p = 0; p < RR; p++) {
            float a[8], b[8];
            *(float4*)(a)     = *(const float4*)&Ts[p * 128 + ty * 8];
            *(float4*)(a + 4) = *(const float4*)&Ts[p * 128 + ty * 8 + 4];
            *(float4*)(b)     = *(const float4*)&Bl[p * 128 + tx * 8];
            *(float4*)(b + 4) = *(const float4*)&Bl[p * 128 + tx * 8 + 4];
            #pragma unroll
            for (int i = 0; i < 8; i++)
                #pragma unroll
                for (int j = 0; j < 8; j++)
                    acc[i][j] = fmaf(a[i], b[j], acc[i][j]);
        }
    }

    // -------- store in [b*H+h][s][dk] layout
    float* dst = (mat == 0) ? g_Q : (mat == 1) ? g_K : g_V;
    int col0 = jn + tx * 8;          // 8 consecutive cols, same head
    int h    = col0 >> 6;
    int dk   = col0 & 63;
    #pragma unroll
    for (int i = 0; i < 8; i++) {
        int n  = bm + ty * 8 + i;
        int b_ = n >> 11;
        int s_ = n & (SS - 1);
        float* o = dst + ((size_t)((b_ * HH + h) * SS + s_)) * DK + dk;
        *(float4*)(o)     = make_float4(acc[i][0], acc[i][1], acc[i][2], acc[i][3]);
        *(float4*)(o + 4) = make_float4(acc[i][4], acc[i][5], acc[i][6], acc[i][7]);
    }
}

// ====================================================================
// Kernel 3: flash attention, fp32
// CTA = (q-block of 64, b*H+h). 64-key tiles, online softmax.
// 256 threads (16x16), 4x4 micro-tile on both score and output tiles.
// ====================================================================
#define SROW 68                      // padded row stride (floats), 16B-aligned
#define ATTN_SMEM (5 * 64 * SROW * 4)

__global__ __launch_bounds__(256, 2) void attn_kernel(
    const float* __restrict__ bias)
{
    extern __shared__ float sm[];
    float* Qs = sm;
    float* Ks = sm + 1 * 64 * SROW;
    float* Vs = sm + 2 * 64 * SROW;
    float* Ps = sm + 3 * 64 * SROW;
    float* Bb = sm + 4 * 64 * SROW;

    int qb = blockIdx.x;             // 0..31
    int bh = blockIdx.y;             // 0..63
    int b_ = bh >> 4;
    int h  = bh & 15;
    int tid = threadIdx.x;
    int tx = tid & 15;
    int ty = tid >> 4;

    const float* Qg = g_Q + ((size_t)bh * SS + qb * 64) * DK;
    const float* Kg = g_K + (size_t)bh * SS * DK;
    const float* Vg = g_V + (size_t)bh * SS * DK;
    const float* Bg = bias + ((size_t)h * SS + qb * 64) * SS;

    // load Q tile
    for (int i = tid; i < 64 * 16; i += 256) {
        int r = i >> 4;
        int c = (i & 15) * 4;
        *(float4*)&Qs[r * SROW + c] = *(const float4*)&Qg[r * DK + c];
    }

    float mrow[4], lrow[4], Oa[4][4];
    #pragma unroll
    for (int i = 0; i < 4; i++) {
        mrow[i] = -1e30f;
        lrow[i] = 0.0f;
        #pragma unroll
        for (int j = 0; j < 4; j++) Oa[i][j] = 0.0f;
    }

    for (int kb = 0; kb < 32; kb++) {
        int kbase = kb * 64;
        __syncthreads();             // prev iter's Ps/Vs reads done; Qs visible
        for (int i = tid; i < 64 * 16; i += 256) {
            int r = i >> 4;
            int c = (i & 15) * 4;
            *(float4*)&Ks[r * SROW + c] = *(const float4*)&Kg[(size_t)(kbase + r) * DK + c];
            *(float4*)&Vs[r * SROW + c] = *(const float4*)&Vg[(size_t)(kbase + r) * DK + c];
            *(float4*)&Bb[r * SROW + c] = *(const float4*)&Bg[(size_t)r * SS + kbase + c];
        }
        __syncthreads();

        // scores = Q K^T + bias  (4x4 per thread)
        float s[4][4];
        #pragma unroll
        for (int i = 0; i < 4; i++) {
            float4 bv = *(const float4*)&Bb[(ty * 4 + i) * SROW + tx * 4];
            s[i][0] = bv.x; s[i][1] = bv.y; s[i][2] = bv.z; s[i][3] = bv.w;
        }
        #pragma unroll
        for (int d0 = 0; d0 < DK; d0 += 4) {
            float4 q[4], kk[4];
            #pragma unroll
            for (int i = 0; i < 4; i++) q[i]  = *(const float4*)&Qs[(ty * 4 + i) * SROW + d0];
            #pragma unroll
            for (int j = 0; j < 4; j++) kk[j] = *(const float4*)&Ks[(tx * 4 + j) * SROW + d0];
            #pragma unroll
            for (int i = 0; i < 4; i++)
                #pragma unroll
                for (int j = 0; j < 4; j++)
                    s[i][j] += q[i].x * kk[j].x + q[i].y * kk[j].y
                             + q[i].z * kk[j].z + q[i].w * kk[j].w;
        }

        // online softmax update, row stats across the 16-lane tx group
        #pragma unroll
        for (int i = 0; i < 4; i++) {
            float mloc = fmaxf(fmaxf(s[i][0], s[i][1]), fmaxf(s[i][2], s[i][3]));
            #pragma unroll
            for (int o = 8; o > 0; o >>= 1)
                mloc = fmaxf(mloc, __shfl_xor_sync(0xffffffffu, mloc, o, 16));
            float mnew = fmaxf(mrow[i], mloc);
            float corr = __expf(mrow[i] - mnew);
            float rs = 0.0f;
            #pragma unroll
            for (int j = 0; j < 4; j++) {
                s[i][j] = __expf(s[i][j] - mnew);
                rs += s[i][j];
            }
            #pragma unroll
            for (int o = 8; o > 0; o >>= 1)
                rs += __shfl_xor_sync(0xffffffffu, rs, o, 16);
            lrow[i] = lrow[i] * corr + rs;
            mrow[i] = mnew;
            #pragma unroll
            for (int j = 0; j < 4; j++) Oa[i][j] *= corr;
            *(float4*)&Ps[(ty * 4 + i) * SROW + tx * 4] =
                make_float4(s[i][0], s[i][1], s[i][2], s[i][3]);
        }
        __syncthreads();

        // O += P @ V
        #pragma unroll
        for (int k0 = 0; k0 < 64; k0 += 4) {
            float4 p[4];
            #pragma unroll
            for (int i = 0; i < 4; i++) p[i] = *(const float4*)&Ps[(ty * 4 + i) * SROW + k0];
            float4 v0 = *(const float4*)&Vs[(k0 + 0) * SROW + tx * 4];
            float4 v1 = *(const float4*)&Vs[(k0 + 1) * SROW + tx * 4];
            float4 v2 = *(const float4*)&Vs[(k0 + 2) * SROW + tx * 4];
            float4 v3 = *(const float4*)&Vs[(k0 + 3) * SROW + tx * 4];
            #pragma unroll
            for (int i = 0; i < 4; i++) {
                Oa[i][0] += p[i].x * v0.x + p[i].y * v1.x + p[i].z * v2.x + p[i].w * v3.x;
                Oa[i][1] += p[i].x * v0.y + p[i].y * v1.y + p[i].z * v2.y + p[i].w * v3.y;
                Oa[i][2] += p[i].x * v0.z + p[i].y * v1.z + p[i].z * v2.z + p[i].w * v3.z;
                Oa[i][3] += p[i].x * v0.w + p[i].y * v1.w + p[i].z * v2.w + p[i].w * v3.w;
            }
        }
    }

    // epilogue: normalize and write to g_O in [n][h*64+dk] layout
    #pragma unroll
    for (int i = 0; i < 4; i++) {
        float inv = 1.0f / lrow[i];
        int row = qb * 64 + ty * 4 + i;
        float* o = g_O + ((size_t)(b_ * SS + row)) * DD + h * DK + tx * 4;
        *(float4*)o = make_float4(Oa[i][0] * inv, Oa[i][1] * inv,
                                  Oa[i][2] * inv, Oa[i][3] * inv);
    }
}

// ====================================================================
// Kernel 4: output projection  out = g_O @ Wo^T   [8192,1024]
// ====================================================================
__global__ __launch_bounds__(256) void out_gemm_kernel(
    const float* __restrict__ Wo,
    float* __restrict__ out)
{
    __shared__ float As[8 * 128];
    __shared__ float Bs[8 * 128];

    int jn = blockIdx.x * 128;       // 0..7 tiles
    int bm = blockIdx.y * 128;

    int tid = threadIdx.x;
    int tx  = tid & 15;
    int ty  = tid >> 4;
    int lr  = tid >> 1;
    int lk  = (tid & 1) * 4;

    const float* Ap = g_O + (size_t)(bm + lr) * DD + lk;
    const float* Bp = Wo  + (size_t)(jn + lr) * DD + lk;

    float acc[8][8];
    #pragma unroll
    for (int i = 0; i < 8; i++)
        #pragma unroll
        for (int j = 0; j < 8; j++) acc[i][j] = 0.0f;

    for (int k0 = 0; k0 < DD; k0 += 8) {
        float4 av = *(const float4*)(Ap + k0);
        float4 bv = *(const float4*)(Bp + k0);
        As[(lk + 0) * 128 + lr] = av.x;
        As[(lk + 1) * 128 + lr] = av.y;
        As[(lk + 2) * 128 + lr] = av.z;
        As[(lk + 3) * 128 + lr] = av.w;
        Bs[(lk + 0) * 128 + lr] = bv.x;
        Bs[(lk + 1) * 128 + lr] = bv.y;
        Bs[(lk + 2) * 128 + lr] = bv.z;
        Bs[(lk + 3) * 128 + lr] = bv.w;
        __syncthreads();

        #pragma unroll
        for (int k = 0; k < 8; k++) {
            float a[8], b[8];
            *(float4*)(a)     = *(const float4*)&As[k * 128 + ty * 8];
            *(float4*)(a + 4) = *(const float4*)&As[k * 128 + ty * 8 + 4];
            *(float4*)(b)     = *(const float4*)&Bs[k * 128 + tx * 8];
            *(float4*)(b + 4) = *(const float4*)&Bs[k * 128 + tx * 8 + 4];
            #pragma unroll
            for (int i = 0; i < 8; i++)
                #pragma unroll
                for (int j = 0; j < 8; j++)
                    acc[i][j] = fmaf(a[i], b[j], acc[i][j]);
        }
        __syncthreads();
    }

    #pragma unroll
    for (int i = 0; i < 8; i++) {
        int n = bm + ty * 8 + i;
        float* o = out + (size_t)n * DD + jn + tx * 8;
        *(float4*)(o)     = make_float4(acc[i][0], acc[i][1], acc[i][2], acc[i][3]);
        *(float4*)(o + 4) = make_float4(acc[i][4], acc[i][5], acc[i][6], acc[i][7]);
    }
}

// ====================================================================
// launch
// inputs: 0 hidden_states, 1 position_bias, 2 Wq, 3 Wk, 4 Wv, 5 Wo,
//         6 Aq, 7 Bq, 8 Av, 9 Bv
// ====================================================================
extern "C" void kernel_launch(void* const* d_in, const int* in_sizes, int n_in,
                              void* d_out, int out_size)
{
    const float* x    = (const float*)d_in[0];
    const float* bias = (const float*)d_in[1];
    const float* Wq   = (const float*)d_in[2];
    const float* Wk   = (const float*)d_in[3];
    const float* Wv   = (const float*)d_in[4];
    const float* Wo   = (const float*)d_in[5];
    const float* Aq   = (const float*)d_in[6];
    const float* Bq   = (const float*)d_in[7];
    const float* Av   = (const float*)d_in[8];
    const float* Bv   = (const float*)d_in[9];
    float* out = (float*)d_out;

    cudaFuncSetAttribute(attn_kernel,
                         cudaFuncAttributeMaxDynamicSharedMemorySize, ATTN_SMEM);

    // 1. LoRA down-proj
    lora_t_kernel<<<(NROWS * 32) / 256, 256>>>(x, Aq, Av);

    // 2. fused QKV projection (+ LoRA epilogue)
    qkv_gemm_kernel<<<dim3(24, NROWS / 128), 256>>>(x, Wq, Wk, Wv, Bq, Bv);

    // 3. flash attention
    attn_kernel<<<dim3(SS / 64, BB * HH), 256, ATTN_SMEM>>>(bias);

    // 4. output projection
    out_gemm_kernel<<<dim3(DD / 128, NROWS / 128), 256>>>(Wo, out);
}

// round 5
// speedup vs baseline: 1.2937x; 1.2937x over previous
#include <cuda_runtime.h>
#include <cuda_bf16.h>
#include <cstdint>
#include <math.h>

// ---------------- problem constants ----------------
#define BB      4
#define SS      2048
#define DD      1024
#define HH      16
#define DK      64
#define RR      16
#define SCALING 2.0f
#define NROWS   (BB * SS)          // 8192

// ---------------- device scratch (no allocs allowed) ----------------
__device__ float g_tq[NROWS * RR];
__device__ float g_tv[NROWS * RR];
__device__ float g_Q[BB * HH * SS * DK];   // [b*H+h][s][dk]
__device__ float g_K[BB * HH * SS * DK];
__device__ float g_V[BB * HH * SS * DK];

// bf16 hi/lo split operands
__device__ __nv_bfloat16 g_xhi[NROWS * DD];
__device__ __nv_bfloat16 g_xlo[NROWS * DD];
__device__ __nv_bfloat16 g_wqkvhi[3 * DD * DD];   // [Wq;Wk;Wv]  (3072,1024)
__device__ __nv_bfloat16 g_wqkvlo[3 * DD * DD];
__device__ __nv_bfloat16 g_wohi[DD * DD];
__device__ __nv_bfloat16 g_wolo[DD * DD];
__device__ __nv_bfloat16 g_Ohi[NROWS * DD];       // attention output, split
__device__ __nv_bfloat16 g_Olo[NROWS * DD];

// ====================================================================
// helpers (sm_100-safe: ldmatrix / mma.sync / cp.async only)
// ====================================================================
__device__ __forceinline__ uint32_t smem_u32(const void* p) {
    uint32_t a;
    asm("{ .reg .u64 t; cvta.to.shared.u64 t, %1; cvt.u32.u64 %0, t; }"
        : "=r"(a) : "l"(p));
    return a;
}

#define LDSM_X4(r, a)                                                          \
    asm volatile("ldmatrix.sync.aligned.m8n8.x4.shared.b16 {%0,%1,%2,%3}, [%4];" \
        : "=r"((r)[0]), "=r"((r)[1]), "=r"((r)[2]), "=r"((r)[3]) : "r"(a))
#define LDSM_X2(r, a)                                                          \
    asm volatile("ldmatrix.sync.aligned.m8n8.x2.shared.b16 {%0,%1}, [%2];"     \
        : "=r"((r)[0]), "=r"((r)[1]) : "r"(a))

#define MMA_BF16(d, a, b)                                                      \
    asm volatile("mma.sync.aligned.m16n8k16.row.col.f32.bf16.bf16.f32 "        \
        "{%0,%1,%2,%3}, {%4,%5,%6,%7}, {%8,%9}, {%0,%1,%2,%3};"                \
        : "+f"((d)[0]), "+f"((d)[1]), "+f"((d)[2]), "+f"((d)[3])               \
        : "r"((a)[0]), "r"((a)[1]), "r"((a)[2]), "r"((a)[3]),                  \
          "r"((b)[0]), "r"((b)[1]))

#define CP_ASYNC16(dst, src)                                                   \
    asm volatile("cp.async.cg.shared.global [%0], [%1], 16;"                   \
        :: "r"(dst), "l"(__cvta_generic_to_global(src)))
#define CP_COMMIT()  asm volatile("cp.async.commit_group;" ::: "memory")
#define CP_WAIT1()   asm volatile("cp.async.wait_group 1;" ::: "memory")
#define CP_WAIT0()   asm volatile("cp.async.wait_group 0;" ::: "memory")

__device__ __forceinline__ uint32_t sw128(int off) {
    return (uint32_t)(off ^ ((off >> 3) & 0x70));
}

// ====================================================================
// Kernel 0: split inputs + weights into bf16 hi/lo
// ====================================================================
#define F4_X (NROWS * DD / 4)      // 2097152
#define F4_W (DD * DD / 4)         // 262144
#define F4_TOTAL (F4_X + 4 * F4_W)

__global__ __launch_bounds__(256) void convert_kernel(
    const float* __restrict__ x,
    const float* __restrict__ Wq, const float* __restrict__ Wk,
    const float* __restrict__ Wv, const float* __restrict__ Wo)
{
    int i = blockIdx.x * blockDim.x + threadIdx.x;
    if (i >= F4_TOTAL) return;

    const float* src;
    __nv_bfloat16 *dh, *dl;
    size_t srcIdx, dstIdx;
    if (i < F4_X) {
        src = x; dh = g_xhi; dl = g_xlo; srcIdx = i; dstIdx = i;
    } else {
        int j = i - F4_X;
        if (j < F4_W)          { src = Wq; srcIdx = j;            dh = g_wqkvhi; dl = g_wqkvlo; dstIdx = j; }
        else if (j < 2 * F4_W) { src = Wk; srcIdx = j - F4_W;     dh = g_wqkvhi; dl = g_wqkvlo; dstIdx = j; }
        else if (j < 3 * F4_W) { src = Wv; srcIdx = j - 2 * F4_W; dh = g_wqkvhi; dl = g_wqkvlo; dstIdx = j; }
        else                   { src = Wo; srcIdx = j - 3 * F4_W; dh = g_wohi;   dl = g_wolo;   dstIdx = srcIdx; }
    }
    float4 v = ((const float4*)src)[srcIdx];
    float vv[4] = {v.x, v.y, v.z, v.w};
    unsigned short hb[4], lb[4];
    #pragma unroll
    for (int k = 0; k < 4; k++) {
        __nv_bfloat16 h = __float2bfloat16(vv[k]);
        float lo = vv[k] - __bfloat162float(h);
        hb[k] = __bfloat16_as_ushort(h);
        lb[k] = __bfloat16_as_ushort(__float2bfloat16(lo));
    }
    uint2 ph, pl;
    ph.x = (uint32_t)hb[0] | ((uint32_t)hb[1] << 16);
    ph.y = (uint32_t)hb[2] | ((uint32_t)hb[3] << 16);
    pl.x = (uint32_t)lb[0] | ((uint32_t)lb[1] << 16);
    pl.y = (uint32_t)lb[2] | ((uint32_t)lb[3] << 16);
    *(uint2*)(dh + dstIdx * 4) = ph;
    *(uint2*)(dl + dstIdx * 4) = pl;
}

// ====================================================================
// Kernel 1: LoRA down-projections  t = (x @ A^T) * SCALING
// ====================================================================
__global__ __launch_bounds__(256) void lora_t_kernel(
    const float* __restrict__ x,
    const float* __restrict__ Aq,
    const float* __restrict__ Av)
{
    int gtid = blockIdx.x * blockDim.x + threadIdx.x;
    int warp = gtid >> 5;
    int lane = gtid & 31;
    if (warp >= NROWS) return;

    const float* Arow = ((lane < 16) ? Aq : Av) + (size_t)(lane & 15) * DD;
    const float* xrow = x + (size_t)warp * DD;

    float acc = 0.0f;
    #pragma unroll 4
    for (int d = 0; d < DD; d += 4) {
        float4 xv = *(const float4*)(xrow + d);
        float4 av = *(const float4*)(Arow + d);
        acc += xv.x * av.x + xv.y * av.y + xv.z * av.z + xv.w * av.w;
    }
    acc *= SCALING;
    if (lane < 16) g_tq[warp * RR + lane]        = acc;
    else           g_tv[warp * RR + (lane & 15)] = acc;
}

// ====================================================================
// Kernel 2: mma.sync split-bf16 GEMM, 128x128 tile, K staged in 64s.
//   mode 0: C[8192,3072] = x @ Wqkv^T  (+LoRA for Q,V) -> g_Q/g_K/g_V
//   mode 1: C[8192,1024] = O @ Wo^T                    -> d_out
// 256 threads (8 warps, 4x2), cp.async double-buffer.
// smem: buf b at b*65536; within buf: Ahi/Alo/Whi/Wlo 16KB each,
// rows of 64 bf16 = 128B, SW128 swizzled.
// ====================================================================
#define GEMM_SMEM (2 * 65536)

__device__ __forceinline__ void issue_stage(
    uint32_t b0,
    const __nv_bfloat16* __restrict__ Ahi, const __nv_bfloat16* __restrict__ Alo,
    const __nv_bfloat16* __restrict__ Whi, const __nv_bfloat16* __restrict__ Wlo,
    int bm, int wrow, int k0, int tid)
{
    #pragma unroll
    for (int t = 0; t < 4; t++) {
        const __nv_bfloat16* src = (t == 0) ? Ahi : (t == 1) ? Alo : (t == 2) ? Whi : Wlo;
        int rb = (t < 2) ? bm : wrow;
        uint32_t dstb = b0 + t * 16384;
        #pragma unroll
        for (int i = 0; i < 4; i++) {
            int idx = i * 256 + tid;     // 1024 chunks of 16B per tile
            int row = idx >> 3;
            int c   = idx & 7;
            int off = row * 128 + c * 16;
            CP_ASYNC16(dstb + sw128(off),
                       src + (size_t)(rb + row) * DD + k0 + c * 8);
        }
    }
}

__global__ __launch_bounds__(256, 1) void mma_gemm_kernel(
    const float* __restrict__ LBq,
    const float* __restrict__ LBv,
    float* __restrict__ out, int mode)
{
    extern __shared__ char smem[];
    uint32_t sb = smem_u32(smem);
    int tid  = threadIdx.x;
    int wid  = tid >> 5;
    int lane = tid & 31;

    int ct   = blockIdx.x;             // column tile
    int bm   = blockIdx.y * 128;       // row base
    int wrow = ct * 128;               // row base into W

    const __nv_bfloat16 *Ahi, *Alo, *Whi, *Wlo;
    if (mode == 0) { Ahi = g_xhi; Alo = g_xlo; Whi = g_wqkvhi; Wlo = g_wqkvlo; }
    else           { Ahi = g_Ohi; Alo = g_Olo; Whi = g_wohi;   Wlo = g_wolo;   }

    issue_stage(sb,         Ahi, Alo, Whi, Wlo, bm, wrow, 0,  tid); CP_COMMIT();
    issue_stage(sb + 65536, Ahi, Alo, Whi, Wlo, bm, wrow, 64, tid); CP_COMMIT();

    int warp_m = wid & 3;              // 4 row-groups of 32
    int warp_n = wid >> 2;             // 2 col-groups of 64

    float acc[2][8][4];
    #pragma unroll
    for (int a = 0; a < 2; a++)
        #pragma unroll
        for (int b = 0; b < 8; b++)
            #pragma unroll
            for (int c = 0; c < 4; c++) acc[a][b][c] = 0.0f;

    for (int s = 0; s < 16; s++) {
        if (s < 15) CP_WAIT1(); else CP_WAIT0();
        __syncthreads();
        uint32_t b0 = sb + (s & 1) * 65536;

        #pragma unroll
        for (int kc = 0; kc < 4; kc++) {
            int kb = kc * 32;          // byte offset of 16-wide k chunk
            uint32_t ah[2][4], al[2][4];
            #pragma unroll
            for (int mt = 0; mt < 2; mt++) {
                int row = warp_m * 32 + mt * 16 + (lane & 15);
                uint32_t sw = sw128(row * 128 + kb + (lane >> 4) * 16);
                LDSM_X4(ah[mt], b0 + sw);
                LDSM_X4(al[mt], b0 + 16384 + sw);
            }
            #pragma unroll
            for (int nt = 0; nt < 8; nt++) {
                int l = lane & 15;
                int row = warp_n * 64 + nt * 8 + (l & 7);
                uint32_t sw = sw128(row * 128 + kb + ((l >> 3) & 1) * 16);
                uint32_t bh[2], bl[2];
                LDSM_X2(bh, b0 + 32768 + sw);
                LDSM_X2(bl, b0 + 49152 + sw);
                #pragma unroll
                for (int mt = 0; mt < 2; mt++) {
                    MMA_BF16(acc[mt][nt], ah[mt], bh);
                    MMA_BF16(acc[mt][nt], ah[mt], bl);
                    MMA_BF16(acc[mt][nt], al[mt], bh);
                }
            }
        }
        __syncthreads();
        if (s + 2 < 16) {
            issue_stage(sb + (s & 1) * 65536, Ahi, Alo, Whi, Wlo,
                        bm, wrow, (s + 2) * 64, tid);
            CP_COMMIT();
        }
    }

    // ------------- epilogue -------------
    int mat = (mode == 0) ? (ct >> 3) : -1;          // 0=q 1=k 2=v
    int jn  = (mode == 0) ? ((ct & 7) * 128) : (ct * 128);
    bool dolora = (mode == 0) && (mat != 1);
    int g = lane >> 2, tg = lane & 3;

    if (dolora) {
        const float* T  = (mat == 0) ? g_tq : g_tv;
        const float* Bm = (mat == 0) ? LBq : LBv;
        float* Bls = (float*)smem;                    // [128 cols][16] = 8KB
        for (int idx = tid; idx < 128 * RR; idx += 256)
            Bls[idx] = Bm[(size_t)jn * RR + idx];
        float tvals[4][RR];                           // 4 rows handled by thread
        #pragma unroll
        for (int r = 0; r < 4; r++) {
            int m = bm + warp_m * 32 + (r >> 1) * 16 + (r & 1) * 8 + g;
            #pragma unroll
            for (int p = 0; p < RR; p += 4)
                *(float4*)&tvals[r][p] = *(const float4*)&T[(size_t)m * RR + p];
        }
        __syncthreads();
        #pragma unroll
        for (int mt = 0; mt < 2; mt++)
            #pragma unroll
            for (int nt = 0; nt < 8; nt++) {
                int c = warp_n * 64 + nt * 8 + tg * 2;
                float a0 = 0, a1 = 0, a2 = 0, a3 = 0;
                #pragma unroll
                for (int p = 0; p < RR; p++) {
                    float b0v = Bls[c * RR + p], b1v = Bls[(c + 1) * RR + p];
                    a0 = fmaf(tvals[mt * 2][p],     b0v, a0);
                    a1 = fmaf(tvals[mt * 2][p],     b1v, a1);
                    a2 = fmaf(tvals[mt * 2 + 1][p], b0v, a2);
                    a3 = fmaf(tvals[mt * 2 + 1][p], b1v, a3);
                }
                acc[mt][nt][0] += a0; acc[mt][nt][1] += a1;
                acc[mt][nt][2] += a2; acc[mt][nt][3] += a3;
            }
    }

    #pragma unroll
    for (int mt = 0; mt < 2; mt++)
        #pragma unroll
        for (int nt = 0; nt < 8; nt++) {
            int c  = jn + warp_n * 64 + nt * 8 + tg * 2;
            int m0 = bm + warp_m * 32 + mt * 16 + g;
            int m1 = m0 + 8;
            if (mode == 0) {
                int h = c >> 6, dk = c & 63;
                float* base = (mat == 0) ? g_Q : (mat == 1) ? g_K : g_V;
                int b0_ = m0 >> 11, s0_ = m0 & (SS - 1);
                int b1_ = m1 >> 11, s1_ = m1 & (SS - 1);
                *(float2*)(base + ((size_t)((b0_ * HH + h) * SS + s0_)) * DK + dk) =
                    make_float2(acc[mt][nt][0], acc[mt][nt][1]);
                *(float2*)(base + ((size_t)((b1_ * HH + h) * SS + s1_)) * DK + dk) =
                    make_float2(acc[mt][nt][2], acc[mt][nt][3]);
            } else {
                *(float2*)(out + (size_t)m0 * DD + c) =
                    make_float2(acc[mt][nt][0], acc[mt][nt][1]);
                *(float2*)(out + (size_t)m1 * DD + c) =
                    make_float2(acc[mt][nt][2], acc[mt][nt][3]);
            }
        }
}

// ====================================================================
// Kernel 3: flash attention, fp32 SIMT (writes O as bf16 hi/lo)
// ====================================================================
#define SROW 68
#define ATTN_SMEM (5 * 64 * SROW * 4)

__global__ __launch_bounds__(256, 2) void attn_kernel(
    const float* __restrict__ bias)
{
    extern __shared__ float sm[];
    float* Qs = sm;
    float* Ks = sm + 1 * 64 * SROW;
    float* Vs = sm + 2 * 64 * SROW;
    float* Ps = sm + 3 * 64 * SROW;
    float* Bb = sm + 4 * 64 * SROW;

    int qb = blockIdx.x;
    int bh = blockIdx.y;
    int b_ = bh >> 4;
    int h  = bh & 15;
    int tid = threadIdx.x;
    int tx = tid & 15;
    int ty = tid >> 4;

    const float* Qg = g_Q + ((size_t)bh * SS + qb * 64) * DK;
    const float* Kg = g_K + (size_t)bh * SS * DK;
    const float* Vg = g_V + (size_t)bh * SS * DK;
    const float* Bg = bias + ((size_t)h * SS + qb * 64) * SS;

    for (int i = tid; i < 64 * 16; i += 256) {
        int r = i >> 4;
        int c = (i & 15) * 4;
        *(float4*)&Qs[r * SROW + c] = *(const float4*)&Qg[r * DK + c];
    }

    float mrow[4], lrow[4], Oa[4][4];
    #pragma unroll
    for (int i = 0; i < 4; i++) {
        mrow[i] = -1e30f;
        lrow[i] = 0.0f;
        #pragma unroll
        for (int j = 0; j < 4; j++) Oa[i][j] = 0.0f;
    }

    for (int kb = 0; kb < 32; kb++) {
        int kbase = kb * 64;
        __syncthreads();
        for (int i = tid; i < 64 * 16; i += 256) {
            int r = i >> 4;
            int c = (i & 15) * 4;
            *(float4*)&Ks[r * SROW + c] = *(const float4*)&Kg[(size_t)(kbase + r) * DK + c];
            *(float4*)&Vs[r * SROW + c] = *(const float4*)&Vg[(size_t)(kbase + r) * DK + c];
            *(float4*)&Bb[r * SROW + c] = *(const float4*)&Bg[(size_t)r * SS + kbase + c];
        }
        __syncthreads();

        float s[4][4];
        #pragma unroll
        for (int i = 0; i < 4; i++) {
            float4 bv = *(const float4*)&Bb[(ty * 4 + i) * SROW + tx * 4];
            s[i][0] = bv.x; s[i][1] = bv.y; s[i][2] = bv.z; s[i][3] = bv.w;
        }
        #pragma unroll
        for (int d0 = 0; d0 < DK; d0 += 4) {
            float4 q[4], kk[4];
            #pragma unroll
            for (int i = 0; i < 4; i++) q[i]  = *(const float4*)&Qs[(ty * 4 + i) * SROW + d0];
            #pragma unroll
            for (int j = 0; j < 4; j++) kk[j] = *(const float4*)&Ks[(tx * 4 + j) * SROW + d0];
            #pragma unroll
            for (int i = 0; i < 4; i++)
                #pragma unroll
                for (int j = 0; j < 4; j++)
                    s[i][j] += q[i].x * kk[j].x + q[i].y * kk[j].y
                             + q[i].z * kk[j].z + q[i].w * kk[j].w;
        }

        #pragma unroll
        for (int i = 0; i < 4; i++) {
            float mloc = fmaxf(fmaxf(s[i][0], s[i][1]), fmaxf(s[i][2], s[i][3]));
            #pragma unroll
            for (int o = 8; o > 0; o >>= 1)
                mloc = fmaxf(mloc, __shfl_xor_sync(0xffffffffu, mloc, o, 16));
            float mnew = fmaxf(mrow[i], mloc);
            float corr = __expf(mrow[i] - mnew);
            float rs = 0.0f;
            #pragma unroll
            for (int j = 0; j < 4; j++) {
                s[i][j] = __expf(s[i][j] - mnew);
                rs += s[i][j];
            }
            #pragma unroll
            for (int o = 8; o > 0; o >>= 1)
                rs += __shfl_xor_sync(0xffffffffu, rs, o, 16);
            lrow[i] = lrow[i] * corr + rs;
            mrow[i] = mnew;
            #pragma unroll
            for (int j = 0; j < 4; j++) Oa[i][j] *= corr;
            *(float4*)&Ps[(ty * 4 + i) * SROW + tx * 4] =
                make_float4(s[i][0], s[i][1], s[i][2], s[i][3]);
        }
        __syncthreads();

        #pragma unroll
        for (int k0 = 0; k0 < 64; k0 += 4) {
            float4 p[4];
            #pragma unroll
            for (int i = 0; i < 4; i++) p[i] = *(const float4*)&Ps[(ty * 4 + i) * SROW + k0];
            float4 v0 = *(const float4*)&Vs[(k0 + 0) * SROW + tx * 4];
            float4 v1 = *(const float4*)&Vs[(k0 + 1) * SROW + tx * 4];
            float4 v2 = *(const float4*)&Vs[(k0 + 2) * SROW + tx * 4];
            float4 v3 = *(const float4*)&Vs[(k0 + 3) * SROW + tx * 4];
            #pragma unroll
            for (int i = 0; i < 4; i++) {
                Oa[i][0] += p[i].x * v0.x + p[i].y * v1.x + p[i].z * v2.x + p[i].w * v3.x;
                Oa[i][1] += p[i].x * v0.y + p[i].y * v1.y + p[i].z * v2.y + p[i].w * v3.y;
                Oa[i][2] += p[i].x * v0.z + p[i].y * v1.z + p[i].z * v2.z + p[i].w * v3.z;
                Oa[i][3] += p[i].x * v0.w + p[i].y * v1.w + p[i].z * v2.w + p[i].w * v3.w;
            }
        }
    }

    // epilogue: normalize, split to bf16 hi/lo, write [n][h*64+dk]
    #pragma unroll
    for (int i = 0; i < 4; i++) {
        float inv = 1.0f / lrow[i];
        int row = qb * 64 + ty * 4 + i;
        size_t base = ((size_t)(b_ * SS + row)) * DD + h * DK + tx * 4;
        unsigned short hb[4], lb[4];
        #pragma unroll
        for (int j = 0; j < 4; j++) {
            float v = Oa[i][j] * inv;
            __nv_bfloat16 hv = __float2bfloat16(v);
            float lo = v - __bfloat162float(hv);
            hb[j] = __bfloat16_as_ushort(hv);
            lb[j] = __bfloat16_as_ushort(__float2bfloat16(lo));
        }
        uint2 ph, pl;
        ph.x = (uint32_t)hb[0] | ((uint32_t)hb[1] << 16);
        ph.y = (uint32_t)hb[2] | ((uint32_t)hb[3] << 16);
        pl.x = (uint32_t)lb[0] | ((uint32_t)lb[1] << 16);
        pl.y = (uint32_t)lb[2] | ((uint32_t)lb[3] << 16);
        *(uint2*)(g_Ohi + base) = ph;
        *(uint2*)(g_Olo + base) = pl;
    }
}

// ====================================================================
// launch
// inputs: 0 hidden_states, 1 position_bias, 2 Wq, 3 Wk, 4 Wv, 5 Wo,
//         6 Aq, 7 Bq, 8 Av, 9 Bv
// ====================================================================
extern "C" void kernel_launch(void* const* d_in, const int* in_sizes, int n_in,
                              void* d_out, int out_size)
{
    const float* x    = (const float*)d_in[0];
    const float* bias = (const float*)d_in[1];
    const float* Wq   = (const float*)d_in[2];
    const float* Wk   = (const float*)d_in[3];
    const float* Wv   = (const float*)d_in[4];
    const float* Wo   = (const float*)d_in[5];
    const float* Aq   = (const float*)d_in[6];
    const float* Bq   = (const float*)d_in[7];
    const float* Av   = (const float*)d_in[8];
    const float* Bv   = (const float*)d_in[9];
    float* out = (float*)d_out;

    cudaFuncSetAttribute(attn_kernel,
                         cudaFuncAttributeMaxDynamicSharedMemorySize, ATTN_SMEM);
    cudaFuncSetAttribute(mma_gemm_kernel,
                         cudaFuncAttributeMaxDynamicSharedMemorySize, GEMM_SMEM);

    // 0. split to bf16 hi/lo
    convert_kernel<<<(F4_TOTAL + 255) / 256, 256>>>(x, Wq, Wk, Wv, Wo);

    // 1. LoRA down-proj
    lora_t_kernel<<<(NROWS * 32) / 256, 256>>>(x, Aq, Av);

    // 2. fused QKV projection (mma.sync, + LoRA epilogue)
    mma_gemm_kernel<<<dim3(24, NROWS / 128), 256, GEMM_SMEM>>>(Bq, Bv, nullptr, 0);

    // 3. flash attention (SIMT fp32)
    attn_kernel<<<dim3(SS / 64, BB * HH), 256, ATTN_SMEM>>>(bias);

    // 4. output projection (mma.sync)
    mma_gemm_kernel<<<dim3(8, NROWS / 128), 256, GEMM_SMEM>>>(nullptr, nullptr, out, 1);
}

// round 6
// speedup vs baseline: 3.4376x; 2.6571x over previous
#include <cuda_runtime.h>
#include <cuda_bf16.h>
#include <cstdint>
#include <math.h>

// ---------------- problem constants ----------------
#define BB      4
#define SS      2048
#define DD      1024
#define HH      16
#define DK      64
#define RR      16
#define SCALING 2.0f
#define NROWS   (BB * SS)          // 8192

// ---------------- device scratch (no allocs allowed) ----------------
__device__ float g_tq[NROWS * RR];
__device__ float g_tv[NROWS * RR];

// bf16 hi/lo split operands
__device__ __nv_bfloat16 g_xhi[NROWS * DD];
__device__ __nv_bfloat16 g_xlo[NROWS * DD];
__device__ __nv_bfloat16 g_wqkvhi[3 * DD * DD];
__device__ __nv_bfloat16 g_wqkvlo[3 * DD * DD];
__device__ __nv_bfloat16 g_wohi[DD * DD];
__device__ __nv_bfloat16 g_wolo[DD * DD];
// Q/K/V split, layout [b*H+h][s][dk]  (64 bf16 = 128B rows)
__device__ __nv_bfloat16 g_Qhi[BB * HH * SS * DK];
__device__ __nv_bfloat16 g_Qlo[BB * HH * SS * DK];
__device__ __nv_bfloat16 g_Khi[BB * HH * SS * DK];
__device__ __nv_bfloat16 g_Klo[BB * HH * SS * DK];
__device__ __nv_bfloat16 g_Vhi[BB * HH * SS * DK];
__device__ __nv_bfloat16 g_Vlo[BB * HH * SS * DK];
// attention output split, layout [b*S+s][h*64+dk]
__device__ __nv_bfloat16 g_Ohi[NROWS * DD];
__device__ __nv_bfloat16 g_Olo[NROWS * DD];

// ====================================================================
// helpers (sm_100-safe: ldmatrix / mma.sync / cp.async only)
// ====================================================================
__device__ __forceinline__ uint32_t smem_u32(const void* p) {
    uint32_t a;
    asm("{ .reg .u64 t; cvta.to.shared.u64 t, %1; cvt.u32.u64 %0, t; }"
        : "=r"(a) : "l"(p));
    return a;
}

#define LDSM_X4(r, a)                                                          \
    asm volatile("ldmatrix.sync.aligned.m8n8.x4.shared.b16 {%0,%1,%2,%3}, [%4];" \
        : "=r"((r)[0]), "=r"((r)[1]), "=r"((r)[2]), "=r"((r)[3]) : "r"(a))
#define LDSM_X4_T(r, a)                                                        \
    asm volatile("ldmatrix.sync.aligned.m8n8.x4.trans.shared.b16 {%0,%1,%2,%3}, [%4];" \
        : "=r"((r)[0]), "=r"((r)[1]), "=r"((r)[2]), "=r"((r)[3]) : "r"(a))
#define LDSM_X2(r, a)                                                          \
    asm volatile("ldmatrix.sync.aligned.m8n8.x2.shared.b16 {%0,%1}, [%2];"     \
        : "=r"((r)[0]), "=r"((r)[1]) : "r"(a))

#define MMA_BF16(d, a, b)                                                      \
    asm volatile("mma.sync.aligned.m16n8k16.row.col.f32.bf16.bf16.f32 "        \
        "{%0,%1,%2,%3}, {%4,%5,%6,%7}, {%8,%9}, {%0,%1,%2,%3};"                \
        : "+f"((d)[0]), "+f"((d)[1]), "+f"((d)[2]), "+f"((d)[3])               \
        : "r"((a)[0]), "r"((a)[1]), "r"((a)[2]), "r"((a)[3]),                  \
          "r"((b)[0]), "r"((b)[1]))

#define CP_ASYNC16(dst, src)                                                   \
    asm volatile("cp.async.cg.shared.global [%0], [%1], 16;"                   \
        :: "r"(dst), "l"(__cvta_generic_to_global(src)))
#define CP_COMMIT()  asm volatile("cp.async.commit_group;" ::: "memory")
#define CP_WAIT1()   asm volatile("cp.async.wait_group 1;" ::: "memory")
#define CP_WAIT0()   asm volatile("cp.async.wait_group 0;" ::: "memory")

__device__ __forceinline__ uint32_t sw128(int off) {
    return (uint32_t)(off ^ ((off >> 3) & 0x70));
}

// split a pair of floats into packed bf16 hi and lo words (low half = first)
__device__ __forceinline__ void pack_hilo(float a, float b,
                                          uint32_t& hi, uint32_t& lo) {
    __nv_bfloat16 ha = __float2bfloat16(a);
    __nv_bfloat16 hb = __float2bfloat16(b);
    __nv_bfloat16 la = __float2bfloat16(a - __bfloat162float(ha));
    __nv_bfloat16 lb = __float2bfloat16(b - __bfloat162float(hb));
    hi = (uint32_t)__bfloat16_as_ushort(ha) | ((uint32_t)__bfloat16_as_ushort(hb) << 16);
    lo = (uint32_t)__bfloat16_as_ushort(la) | ((uint32_t)__bfloat16_as_ushort(lb) << 16);
}

// ====================================================================
// Kernel 0: split inputs + weights into bf16 hi/lo
// ====================================================================
#define F4_X (NROWS * DD / 4)
#define F4_W (DD * DD / 4)
#define F4_TOTAL (F4_X + 4 * F4_W)

__global__ __launch_bounds__(256) void convert_kernel(
    const float* __restrict__ x,
    const float* __restrict__ Wq, const float* __restrict__ Wk,
    const float* __restrict__ Wv, const float* __restrict__ Wo)
{
    int i = blockIdx.x * blockDim.x + threadIdx.x;
    if (i >= F4_TOTAL) return;

    const float* src;
    __nv_bfloat16 *dh, *dl;
    size_t srcIdx, dstIdx;
    if (i < F4_X) {
        src = x; dh = g_xhi; dl = g_xlo; srcIdx = i; dstIdx = i;
    } else {
        int j = i - F4_X;
        if (j < F4_W)          { src = Wq; srcIdx = j;            dh = g_wqkvhi; dl = g_wqkvlo; dstIdx = j; }
        else if (j < 2 * F4_W) { src = Wk; srcIdx = j - F4_W;     dh = g_wqkvhi; dl = g_wqkvlo; dstIdx = j; }
        else if (j < 3 * F4_W) { src = Wv; srcIdx = j - 2 * F4_W; dh = g_wqkvhi; dl = g_wqkvlo; dstIdx = j; }
        else                   { src = Wo; srcIdx = j - 3 * F4_W; dh = g_wohi;   dl = g_wolo;   dstIdx = srcIdx; }
    }
    float4 v = ((const float4*)src)[srcIdx];
    uint32_t h0, l0, h1, l1;
    pack_hilo(v.x, v.y, h0, l0);
    pack_hilo(v.z, v.w, h1, l1);
    *(uint2*)(dh + dstIdx * 4) = make_uint2(h0, h1);
    *(uint2*)(dl + dstIdx * 4) = make_uint2(l0, l1);
}

// ====================================================================
// Kernel 1: LoRA down-projections  t = (x @ A^T) * SCALING
// ====================================================================
__global__ __launch_bounds__(256) void lora_t_kernel(
    const float* __restrict__ x,
    const float* __restrict__ Aq,
    const float* __restrict__ Av)
{
    int gtid = blockIdx.x * blockDim.x + threadIdx.x;
    int warp = gtid >> 5;
    int lane = gtid & 31;
    if (warp >= NROWS) return;

    const float* Arow = ((lane < 16) ? Aq : Av) + (size_t)(lane & 15) * DD;
    const float* xrow = x + (size_t)warp * DD;

    float acc = 0.0f;
    #pragma unroll 4
    for (int d = 0; d < DD; d += 4) {
        float4 xv = *(const float4*)(xrow + d);
        float4 av = *(const float4*)(Arow + d);
        acc += xv.x * av.x + xv.y * av.y + xv.z * av.z + xv.w * av.w;
    }
    acc *= SCALING;
    if (lane < 16) g_tq[warp * RR + lane]        = acc;
    else           g_tv[warp * RR + (lane & 15)] = acc;
}

// ====================================================================
// Kernel 2: mma.sync split-bf16 GEMM, 128x128 tile.
//   mode 0: x @ Wqkv^T (+LoRA) -> g_{Q,K,V}{hi,lo}  (bf16 split out)
//   mode 1: O @ Wo^T           -> d_out (fp32)
// ====================================================================
#define GEMM_SMEM (2 * 65536)

__device__ __forceinline__ void issue_stage(
    uint32_t b0,
    const __nv_bfloat16* __restrict__ Ahi, const __nv_bfloat16* __restrict__ Alo,
    const __nv_bfloat16* __restrict__ Whi, const __nv_bfloat16* __restrict__ Wlo,
    int bm, int wrow, int k0, int tid)
{
    #pragma unroll
    for (int t = 0; t < 4; t++) {
        const __nv_bfloat16* src = (t == 0) ? Ahi : (t == 1) ? Alo : (t == 2) ? Whi : Wlo;
        int rb = (t < 2) ? bm : wrow;
        uint32_t dstb = b0 + t * 16384;
        #pragma unroll
        for (int i = 0; i < 4; i++) {
            int idx = i * 256 + tid;
            int row = idx >> 3;
            int c   = idx & 7;
            CP_ASYNC16(dstb + sw128(row * 128 + c * 16),
                       src + (size_t)(rb + row) * DD + k0 + c * 8);
        }
    }
}

__global__ __launch_bounds__(256, 1) void mma_gemm_kernel(
    const float* __restrict__ LBq,
    const float* __restrict__ LBv,
    float* __restrict__ out, int mode)
{
    extern __shared__ char smem[];
    uint32_t sb = smem_u32(smem);
    int tid  = threadIdx.x;
    int wid  = tid >> 5;
    int lane = tid & 31;

    int ct   = blockIdx.x;
    int bm   = blockIdx.y * 128;
    int wrow = ct * 128;

    const __nv_bfloat16 *Ahi, *Alo, *Whi, *Wlo;
    if (mode == 0) { Ahi = g_xhi; Alo = g_xlo; Whi = g_wqkvhi; Wlo = g_wqkvlo; }
    else           { Ahi = g_Ohi; Alo = g_Olo; Whi = g_wohi;   Wlo = g_wolo;   }

    issue_stage(sb,         Ahi, Alo, Whi, Wlo, bm, wrow, 0,  tid); CP_COMMIT();
    issue_stage(sb + 65536, Ahi, Alo, Whi, Wlo, bm, wrow, 64, tid); CP_COMMIT();

    int warp_m = wid & 3;
    int warp_n = wid >> 2;

    float acc[2][8][4];
    #pragma unroll
    for (int a = 0; a < 2; a++)
        #pragma unroll
        for (int b = 0; b < 8; b++)
            #pragma unroll
            for (int c = 0; c < 4; c++) acc[a][b][c] = 0.0f;

    for (int s = 0; s < 16; s++) {
        if (s < 15) CP_WAIT1(); else CP_WAIT0();
        __syncthreads();
        uint32_t b0 = sb + (s & 1) * 65536;

        #pragma unroll
        for (int kc = 0; kc < 4; kc++) {
            int kb = kc * 32;
            uint32_t ah[2][4], al[2][4];
            #pragma unroll
            for (int mt = 0; mt < 2; mt++) {
                int row = warp_m * 32 + mt * 16 + (lane & 15);
                uint32_t sw = sw128(row * 128 + kb + (lane >> 4) * 16);
                LDSM_X4(ah[mt], b0 + sw);
                LDSM_X4(al[mt], b0 + 16384 + sw);
            }
            #pragma unroll
            for (int nt = 0; nt < 8; nt++) {
                int l = lane & 15;
                int row = warp_n * 64 + nt * 8 + (l & 7);
                uint32_t sw = sw128(row * 128 + kb + ((l >> 3) & 1) * 16);
                uint32_t bh[2], bl[2];
                LDSM_X2(bh, b0 + 32768 + sw);
                LDSM_X2(bl, b0 + 49152 + sw);
                #pragma unroll
                for (int mt = 0; mt < 2; mt++) {
                    MMA_BF16(acc[mt][nt], ah[mt], bh);
                    MMA_BF16(acc[mt][nt], ah[mt], bl);
                    MMA_BF16(acc[mt][nt], al[mt], bh);
                }
            }
        }
        __syncthreads();
        if (s + 2 < 16) {
            issue_stage(sb + (s & 1) * 65536, Ahi, Alo, Whi, Wlo,
                        bm, wrow, (s + 2) * 64, tid);
            CP_COMMIT();
        }
    }

    // ------------- epilogue -------------
    int mat = (mode == 0) ? (ct >> 3) : -1;
    int jn  = (mode == 0) ? ((ct & 7) * 128) : (ct * 128);
    bool dolora = (mode == 0) && (mat != 1);
    int g = lane >> 2, tg = lane & 3;

    if (dolora) {
        const float* T  = (mat == 0) ? g_tq : g_tv;
        const float* Bm = (mat == 0) ? LBq : LBv;
        float* Bls = (float*)smem;
        for (int idx = tid; idx < 128 * RR; idx += 256)
            Bls[idx] = Bm[(size_t)jn * RR + idx];
        float tvals[4][RR];
        #pragma unroll
        for (int r = 0; r < 4; r++) {
            int m = bm + warp_m * 32 + (r >> 1) * 16 + (r & 1) * 8 + g;
            #pragma unroll
            for (int p = 0; p < RR; p += 4)
                *(float4*)&tvals[r][p] = *(const float4*)&T[(size_t)m * RR + p];
        }
        __syncthreads();
        #pragma unroll
        for (int mt = 0; mt < 2; mt++)
            #pragma unroll
            for (int nt = 0; nt < 8; nt++) {
                int c = warp_n * 64 + nt * 8 + tg * 2;
                float a0 = 0, a1 = 0, a2 = 0, a3 = 0;
                #pragma unroll
                for (int p = 0; p < RR; p++) {
                    float b0v = Bls[c * RR + p], b1v = Bls[(c + 1) * RR + p];
                    a0 = fmaf(tvals[mt * 2][p],     b0v, a0);
                    a1 = fmaf(tvals[mt * 2][p],     b1v, a1);
                    a2 = fmaf(tvals[mt * 2 + 1][p], b0v, a2);
                    a3 = fmaf(tvals[mt * 2 + 1][p], b1v, a3);
                }
                acc[mt][nt][0] += a0; acc[mt][nt][1] += a1;
                acc[mt][nt][2] += a2; acc[mt][nt][3] += a3;
            }
    }

    #pragma unroll
    for (int mt = 0; mt < 2; mt++)
        #pragma unroll
        for (int nt = 0; nt < 8; nt++) {
            int c  = jn + warp_n * 64 + nt * 8 + tg * 2;
            int m0 = bm + warp_m * 32 + mt * 16 + g;
            int m1 = m0 + 8;
            if (mode == 0) {
                int h = c >> 6, dk = c & 63;
                __nv_bfloat16 *dhi, *dlo;
                if (mat == 0)      { dhi = g_Qhi; dlo = g_Qlo; }
                else if (mat == 1) { dhi = g_Khi; dlo = g_Klo; }
                else               { dhi = g_Vhi; dlo = g_Vlo; }
                int b0_ = m0 >> 11, s0_ = m0 & (SS - 1);
                int b1_ = m1 >> 11, s1_ = m1 & (SS - 1);
                size_t a0 = ((size_t)((b0_ * HH + h) * SS + s0_)) * DK + dk;
                size_t a1 = ((size_t)((b1_ * HH + h) * SS + s1_)) * DK + dk;
                uint32_t hi, lo;
                pack_hilo(acc[mt][nt][0], acc[mt][nt][1], hi, lo);
                *(uint32_t*)(dhi + a0) = hi; *(uint32_t*)(dlo + a0) = lo;
                pack_hilo(acc[mt][nt][2], acc[mt][nt][3], hi, lo);
                *(uint32_t*)(dhi + a1) = hi; *(uint32_t*)(dlo + a1) = lo;
            } else {
                *(float2*)(out + (size_t)m0 * DD + c) =
                    make_float2(acc[mt][nt][0], acc[mt][nt][1]);
                *(float2*)(out + (size_t)m1 * DD + c) =
                    make_float2(acc[mt][nt][2], acc[mt][nt][3]);
            }
        }
}

// ====================================================================
// Kernel 3: flash attention via mma.sync split-bf16
// CTA = 128 q-rows x (b,h); 8 warps x 16 q-rows; 64-key tiles.
// smem stage: Khi 8K | Klo 8K | Vhi 8K | Vlo 8K | bias 128x68 f32 (34816)
// double-buffered = 135168 B.
// ====================================================================
#define QB        128
#define AS_BIAS   32768
#define AS_STAGE  67584
#define ATTN_SMEM (2 * AS_STAGE)
#define BIAS_STRIDE 68   // floats

__device__ __forceinline__ void attn_issue(
    uint32_t st, size_t kvbase, const float* __restrict__ Bg, int kt, int tid)
{
    int key0 = kt * 64;
    #pragma unroll
    for (int t = 0; t < 4; t++) {
        const __nv_bfloat16* src = (t == 0) ? g_Khi : (t == 1) ? g_Klo
                                 : (t == 2) ? g_Vhi : g_Vlo;
        #pragma unroll
        for (int i = 0; i < 2; i++) {
            int idx = i * 256 + tid;
            int row = idx >> 3, c = idx & 7;
            CP_ASYNC16(st + t * 8192 + sw128(row * 128 + c * 16),
                       src + kvbase + (size_t)(key0 + row) * DK + c * 8);
        }
    }
    #pragma unroll
    for (int i = 0; i < 8; i++) {
        int idx = i * 256 + tid;
        int row = idx >> 4, c = idx & 15;
        CP_ASYNC16(st + AS_BIAS + row * (BIAS_STRIDE * 4) + c * 16,
                   Bg + (size_t)row * SS + key0 + c * 4);
    }
}

__global__ __launch_bounds__(256, 1) void attn_mma_kernel(
    const float* __restrict__ bias)
{
    extern __shared__ char smem[];
    uint32_t sb = smem_u32(smem);
    int tid = threadIdx.x, wid = tid >> 5, lane = tid & 31;
    int qb = blockIdx.x, bh = blockIdx.y;
    int b_ = bh >> 4, h = bh & 15;
    int g = lane >> 2, tq = lane & 3;

    size_t kvbase = (size_t)bh * SS * DK;
    const float* Bg = bias + ((size_t)h * SS + qb * QB) * SS;

    // ---- stage Q (hi at [0,16K), lo at [16K,32K)), ldmatrix to regs
    {
        const __nv_bfloat16* Qh = g_Qhi + kvbase + (size_t)(qb * QB) * DK;
        const __nv_bfloat16* Ql = g_Qlo + kvbase + (size_t)(qb * QB) * DK;
        #pragma unroll
        for (int i = 0; i < 4; i++) {
            int idx = i * 256 + tid;
            int row = idx >> 3, c = idx & 7;
            uint32_t sw = sw128(row * 128 + c * 16);
            CP_ASYNC16(sb + sw,         Qh + (size_t)row * DK + c * 8);
            CP_ASYNC16(sb + 16384 + sw, Ql + (size_t)row * DK + c * 8);
        }
        CP_COMMIT(); CP_WAIT0(); __syncthreads();
    }
    uint32_t qh[4][4], ql[4][4];
    #pragma unroll
    for (int kc = 0; kc < 4; kc++) {
        int row = wid * 16 + (lane & 15);
        uint32_t sw = sw128(row * 128 + kc * 32 + (lane >> 4) * 16);
        LDSM_X4(qh[kc], sb + sw);
        LDSM_X4(ql[kc], sb + 16384 + sw);
    }
    __syncthreads();

    float m0 = -1e30f, m1 = -1e30f, l0 = 0.0f, l1 = 0.0f;
    float acc_o[8][4];
    #pragma unroll
    for (int nt = 0; nt < 8; nt++)
        #pragma unroll
        for (int c = 0; c < 4; c++) acc_o[nt][c] = 0.0f;

    attn_issue(sb,            kvbase, Bg, 0, tid); CP_COMMIT();
    attn_issue(sb + AS_STAGE, kvbase, Bg, 1, tid); CP_COMMIT();

    for (int kt = 0; kt < 32; kt++) {
        if (kt < 31) CP_WAIT1(); else CP_WAIT0();
        __syncthreads();
        uint32_t st = sb + (kt & 1) * AS_STAGE;

        // ---- S = Q K^T (split 3-term)
        float s[8][4];
        #pragma unroll
        for (int nt = 0; nt < 8; nt++)
            #pragma unroll
            for (int c = 0; c < 4; c++) s[nt][c] = 0.0f;

        #pragma unroll
        for (int kc = 0; kc < 4; kc++) {
            #pragma unroll
            for (int j = 0; j < 4; j++) {
                uint32_t kh[4], kl[4];
                int row = (2 * j + ((lane >> 4) & 1)) * 8 + (lane & 7);
                uint32_t sw = sw128(row * 128 + kc * 32 + ((lane >> 3) & 1) * 16);
                LDSM_X4(kh, st + sw);
                LDSM_X4(kl, st + 8192 + sw);
                MMA_BF16(s[2 * j],     qh[kc], kh);
                MMA_BF16(s[2 * j],     qh[kc], kl);
                MMA_BF16(s[2 * j],     ql[kc], kh);
                MMA_BF16(s[2 * j + 1], qh[kc], kh + 2);
                MMA_BF16(s[2 * j + 1], qh[kc], kl + 2);
                MMA_BF16(s[2 * j + 1], ql[kc], kh + 2);
            }
        }

        // ---- add bias
        {
            const float* brow0 = (const float*)(smem + (kt & 1) * AS_STAGE + AS_BIAS)
                               + (wid * 16 + g) * BIAS_STRIDE;
            const float* brow1 = brow0 + 8 * BIAS_STRIDE;
            #pragma unroll
            for (int nt = 0; nt < 8; nt++) {
                float2 v0 = *(const float2*)(brow0 + nt * 8 + tq * 2);
                float2 v1 = *(const float2*)(brow1 + nt * 8 + tq * 2);
                s[nt][0] += v0.x; s[nt][1] += v0.y;
                s[nt][2] += v1.x; s[nt][3] += v1.y;
            }
        }

        // ---- online softmax
        float mx0 = -1e30f, mx1 = -1e30f;
        #pragma unroll
        for (int nt = 0; nt < 8; nt++) {
            mx0 = fmaxf(mx0, fmaxf(s[nt][0], s[nt][1]));
            mx1 = fmaxf(mx1, fmaxf(s[nt][2], s[nt][3]));
        }
        mx0 = fmaxf(mx0, __shfl_xor_sync(0xffffffffu, mx0, 1));
        mx0 = fmaxf(mx0, __shfl_xor_sync(0xffffffffu, mx0, 2));
        mx1 = fmaxf(mx1, __shfl_xor_sync(0xffffffffu, mx1, 1));
        mx1 = fmaxf(mx1, __shfl_xor_sync(0xffffffffu, mx1, 2));
        float mn0 = fmaxf(m0, mx0), mn1 = fmaxf(m1, mx1);
        float c0 = __expf(m0 - mn0), c1 = __expf(m1 - mn1);
        m0 = mn0; m1 = mn1;
        float sum0 = 0.0f, sum1 = 0.0f;
        #pragma unroll
        for (int nt = 0; nt < 8; nt++) {
            s[nt][0] = __expf(s[nt][0] - mn0);
            s[nt][1] = __expf(s[nt][1] - mn0);
            s[nt][2] = __expf(s[nt][2] - mn1);
            s[nt][3] = __expf(s[nt][3] - mn1);
            sum0 += s[nt][0] + s[nt][1];
            sum1 += s[nt][2] + s[nt][3];
        }
        sum0 += __shfl_xor_sync(0xffffffffu, sum0, 1);
        sum0 += __shfl_xor_sync(0xffffffffu, sum0, 2);
        sum1 += __shfl_xor_sync(0xffffffffu, sum1, 1);
        sum1 += __shfl_xor_sync(0xffffffffu, sum1, 2);
        l0 = l0 * c0 + sum0;
        l1 = l1 * c1 + sum1;
        #pragma unroll
        for (int nt = 0; nt < 8; nt++) {
            acc_o[nt][0] *= c0; acc_o[nt][1] *= c0;
            acc_o[nt][2] *= c1; acc_o[nt][3] *= c1;
        }

        // ---- P -> bf16 hi/lo A-fragments
        uint32_t ph[4][4], pl[4][4];
        #pragma unroll
        for (int kk = 0; kk < 4; kk++) {
            pack_hilo(s[2 * kk][0],     s[2 * kk][1],     ph[kk][0], pl[kk][0]);
            pack_hilo(s[2 * kk][2],     s[2 * kk][3],     ph[kk][1], pl[kk][1]);
            pack_hilo(s[2 * kk + 1][0], s[2 * kk + 1][1], ph[kk][2], pl[kk][2]);
            pack_hilo(s[2 * kk + 1][2], s[2 * kk + 1][3], ph[kk][3], pl[kk][3]);
        }

        // ---- O += P V (split 3-term), V via ldmatrix.trans
        #pragma unroll
        for (int kk = 0; kk < 4; kk++) {
            #pragma unroll
            for (int j = 0; j < 4; j++) {
                uint32_t vh[4], vl[4];
                int m_  = lane >> 3;
                int key = kk * 16 + (m_ & 1) * 8 + (lane & 7);
                int dkb = j * 16 + (m_ >> 1) * 8;
                uint32_t sw = sw128(key * 128 + dkb * 2);
                LDSM_X4_T(vh, st + 16384 + sw);
                LDSM_X4_T(vl, st + 24576 + sw);
                MMA_BF16(acc_o[2 * j],     ph[kk], vh);
                MMA_BF16(acc_o[2 * j],     ph[kk], vl);
                MMA_BF16(acc_o[2 * j],     pl[kk], vh);
                MMA_BF16(acc_o[2 * j + 1], ph[kk], vh + 2);
                MMA_BF16(acc_o[2 * j + 1], ph[kk], vl + 2);
                MMA_BF16(acc_o[2 * j + 1], pl[kk], vh + 2);
            }
        }

        __syncthreads();
        if (kt + 2 < 32) {
            attn_issue(sb + (kt & 1) * AS_STAGE, kvbase, Bg, kt + 2, tid);
            CP_COMMIT();
        }
    }

    // ---- epilogue: normalize, split, write g_Ohi/g_Olo
    float i0 = 1.0f / l0, i1 = 1.0f / l1;
    int q0 = qb * QB + wid * 16 + g;
    size_t base0 = ((size_t)(b_ * SS + q0)) * DD + h * DK;
    size_t base1 = base0 + (size_t)8 * DD;
    #pragma unroll
    for (int nt = 0; nt < 8; nt++) {
        int dk = nt * 8 + tq * 2;
        uint32_t hi, lo;
        pack_hilo(acc_o[nt][0] * i0, acc_o[nt][1] * i0, hi, lo);
        *(uint32_t*)(g_Ohi + base0 + dk) = hi;
        *(uint32_t*)(g_Olo + base0 + dk) = lo;
        pack_hilo(acc_o[nt][2] * i1, acc_o[nt][3] * i1, hi, lo);
        *(uint32_t*)(g_Ohi + base1 + dk) = hi;
        *(uint32_t*)(g_Olo + base1 + dk) = lo;
    }
}

// ====================================================================
// launch
// ====================================================================
extern "C" void kernel_launch(void* const* d_in, const int* in_sizes, int n_in,
                              void* d_out, int out_size)
{
    const float* x    = (const float*)d_in[0];
    const float* bias = (const float*)d_in[1];
    const float* Wq   = (const float*)d_in[2];
    const float* Wk   = (const float*)d_in[3];
    const float* Wv   = (const float*)d_in[4];
    const float* Wo   = (const float*)d_in[5];
    const float* Aq   = (const float*)d_in[6];
    const float* Bq   = (const float*)d_in[7];
    const float* Av   = (const float*)d_in[8];
    const float* Bv   = (const float*)d_in[9];
    float* out = (float*)d_out;

    cudaFuncSetAttribute(attn_mma_kernel,
                         cudaFuncAttributeMaxDynamicSharedMemorySize, ATTN_SMEM);
    cudaFuncSetAttribute(mma_gemm_kernel,
                         cudaFuncAttributeMaxDynamicSharedMemorySize, GEMM_SMEM);

    convert_kernel<<<(F4_TOTAL + 255) / 256, 256>>>(x, Wq, Wk, Wv, Wo);
    lora_t_kernel<<<(NROWS * 32) / 256, 256>>>(x, Aq, Av);
    mma_gemm_kernel<<<dim3(24, NROWS / 128), 256, GEMM_SMEM>>>(Bq, Bv, nullptr, 0);
    attn_mma_kernel<<<dim3(SS / QB, BB * HH), 256, ATTN_SMEM>>>(bias);
    mma_gemm_kernel<<<dim3(8, NROWS / 128), 256, GEMM_SMEM>>>(nullptr, nullptr, out, 1);
}